// round 11
// baseline (speedup 1.0000x reference)
#include <cuda_runtime.h>
#include <math.h>

// Problem constants (B=4, F=100, n_peaks=16, W=H=64)
#define B_SZ 4
#define F_SZ 100
#define NP 16
#define PIX 4096
#define TPB 128
#define PPT 2                 // pixels per thread
#define NFC 9                 // 1x12 + 8x11 = 100; grid 16*4*9=576 <= 148*4 one wave
#define FCMAX 12

#define FLT_EPS_F 1.1920929e-7f
#define EXP_S2LD   59.066666f       // exp(sqrt(2*ln(4096)))
#define LOG_NPEAKS 2.7725887f       // ln(16)

#define MAG_COUNT ((size_t)B_SZ * F_SZ * PIX)   // 1,638,400
#define DIR_OFF   MAG_COUNT
#define AUX_OFF   (3 * MAG_COUNT)               // 4,915,200

#define NROWS (B_SZ * F_SZ)                     // 400

__device__ float  g_part[512];                  // per-(b,p) eighth sums of exp(2x)
__device__ float4 g_c[NROWS * NP];              // {cx, cy, cz, 0} per (row, peak)
__device__ float  g_bias[NROWS];                // pre-halved interp bias

// ---------------------------------------------------------------------------
// Kernel 1: fused prep
//   blocks [0,512):    norm partial sums (bp = blk>>3, eighth = blk&7)
//   blocks [512,562):  response precompute + bias
//   block  562:        aux_sparse (fully unrolled loads -> MLP ~50)
// ---------------------------------------------------------------------------
__global__ __launch_bounds__(TPB) void prep_kernel(
    const float* __restrict__ shapes,
    const float* __restrict__ resp,
    const float* __restrict__ freqs,
    float* __restrict__ out_aux)
{
    const int blk = blockIdx.x;
    const int tid = threadIdx.x;
    __shared__ float sh[TPB];

    if (blk < 512) {
        // ---- norm partials: 512 floats per block, 1 float4/thread ----
        const int bp = blk >> 3, oct = blk & 7;
        const int b = bp >> 4, p = bp & 15;
        const float4* x = (const float4*)(shapes + ((size_t)(b * 48 + p)) * PIX + oct * 512);
        float4 v = x[tid];
        float s = __expf(2.f * v.x) + __expf(2.f * v.y)
                + __expf(2.f * v.z) + __expf(2.f * v.w);
        sh[tid] = s; __syncthreads();
        if (tid < 64) sh[tid] += sh[tid + 64];
        __syncthreads();
        if (tid < 32) {
            float v2 = sh[tid] + sh[tid + 32];
            #pragma unroll
            for (int o = 16; o > 0; o >>= 1)
                v2 += __shfl_down_sync(0xffffffff, v2, o);
            if (tid == 0) g_part[blk] = v2;
        }
    } else if (blk < 562) {
        // ---- response precompute: one (row, peak) item per thread ----
        const int idx = (blk - 512) * TPB + tid;    // [0, 6400)
        if (idx < NROWS * NP) {
            const int row = idx >> 4, p = idx & 15;
            const float* rb = resp + (size_t)row * 48;
            float er = __expf(rb[p]);
            float tr = rb[16 + p], ti = rb[32 + p];
            float inv = rsqrtf(fmaxf(tr * tr + ti * ti, FLT_EPS_F));
            g_c[idx] = make_float4(er, er * tr * inv, er * ti * inv, 0.f);
            if (p == 0) {
                float fq  = freqs[row];
                float pos = fminf(fmaxf((fq + 1.0f) * 0.5f * 127.0f, 0.0f), 127.0f);
                float lof = floorf(pos);
                int   lo  = (int)lof;
                int   hi  = min(lo + 1, 127);
                float w   = pos - lof;
                const float k = 3.14159265358979323846f / 127.0f;
                float Tlo = cosf((float)lo * k) * 1.5f - 3.0f;
                float Thi = cosf((float)hi * k) * 1.5f - 3.0f;
                g_bias[row] = 0.5f * (Tlo * (1.0f - w) + Thi * w);
            }
        }
    } else {
        // ---- aux_sparse: 2 threads per (b,p), 50 f's each, FULL unroll ----
        const int bp = tid & 63, g = tid >> 6;
        const int b = bp >> 4, p = bp & 15;
        const float* base = resp + ((size_t)(b * F_SZ) + g * 50) * 48 + p;
        float s = 0.f;
        #pragma unroll
        for (int k = 0; k < 50; k++)
            s += __expf(2.0f * base[(size_t)k * 48]);
        sh[tid] = s; __syncthreads();
        if (tid < 64) {
            float st = sh[tid] + sh[tid + 64];
            float c  = 0.5f * logf(st);
            sh[tid]  = fmaxf(c, 0.0f) + log1pf(__expf(-fabsf(c)));
        }
        __syncthreads();
        if (tid < 32) {
            float v = sh[tid] + sh[tid + 32];
            #pragma unroll
            for (int o = 16; o > 0; o >>= 1)
                v += __shfl_down_sync(0xffffffff, v, o);
            if (tid == 0) *out_aux = v * (1.0f / 64.0f);
        }
    }
}

// ---------------------------------------------------------------------------
// Kernel 2: main field. 2 pixels/thread (float2 I/O), R5 smem layout,
// grid 576 CTAs @ 4/SM = one wave. 4 independent FFMA chains per warp.
// ---------------------------------------------------------------------------
__global__ __launch_bounds__(TPB, 4) void field_kernel(
    const float* __restrict__ shapes,
    float* __restrict__ out)
{
    const int b   = blockIdx.y;
    const int fc  = blockIdx.z;
    const int tid = threadIdx.x;
    const int pix = blockIdx.x * (TPB * PPT) + 2 * tid;

    const int f0  = fc * 11 + min(fc, 1);       // chunk 0: 12, chunks 1..8: 11
    const int len = (fc < 1) ? 12 : 11;

    __shared__ float4 sc[FCMAX][NP];            // {cx,cy,cz,0}
    __shared__ float  sbias[FCMAX];
    __shared__ float  sinvs[NP];

    const int row0 = b * F_SZ + f0;
    {
        const float4* gc = g_c + (size_t)row0 * NP;
        for (int i = tid; i < len * NP; i += TPB)
            ((float4*)sc)[i] = gc[i];
        if (tid < len) sbias[tid] = g_bias[row0 + tid];
        if (tid >= 32 && tid < 32 + NP) {
            const int p = tid - 32;
            const int g8 = (b * NP + p) * 8;
            float S = 0.f;
            #pragma unroll
            for (int k = 0; k < 8; k++) S += g_part[g8 + k];
            sinvs[p] = EXP_S2LD * rsqrtf(S);
        }
    }
    __syncthreads();

    // Per-pixel-pair setup
    float E0[NP], xr0[NP], xi0[NP];
    float E1[NP], xr1[NP], xi1[NP];
    const float* sb = shapes + (size_t)b * 3 * NP * PIX + pix;
    #pragma unroll
    for (int p = 0; p < NP; p++) {
        float2 a  = *(const float2*)(sb + p * PIX);
        float2 r  = *(const float2*)(sb + (NP + p) * PIX);
        float2 im = *(const float2*)(sb + (2 * NP + p) * PIX);
        float iv = sinvs[p];
        float e0 = __expf(a.x) * iv;
        float e1 = __expf(a.y) * iv;
        float n0 = rsqrtf(fmaxf(r.x * r.x + im.x * im.x, FLT_EPS_F));
        float n1 = rsqrtf(fmaxf(r.y * r.y + im.y * im.y, FLT_EPS_F));
        E0[p] = e0; xr0[p] = e0 * r.x * n0; xi0[p] = e0 * im.x * n0;
        E1[p] = e1; xr1[p] = e1 * r.y * n1; xi1[p] = e1 * im.y * n1;
    }

    float* magp = out + (size_t)row0 * PIX + pix;
    float* dirp = out + DIR_OFF + (size_t)row0 * 2 * PIX + pix;

    for (int lf = 0; lf < len; lf++) {
        float sr0 = 0.f, si0 = 0.f, wm0 = 0.f;
        float sr1 = 0.f, si1 = 0.f, wm1 = 0.f;
        #pragma unroll
        for (int p = 0; p < NP; p++) {
            float4 c = sc[lf][p];
            wm0 = fmaxf(wm0, E0[p] * c.x);
            sr0 = fmaf(xr0[p],  c.y, sr0); sr0 = fmaf(-xi0[p], c.z, sr0);
            si0 = fmaf(xr0[p],  c.z, si0); si0 = fmaf(xi0[p],  c.y, si0);
            wm1 = fmaxf(wm1, E1[p] * c.x);
            sr1 = fmaf(xr1[p],  c.y, sr1); sr1 = fmaf(-xi1[p], c.z, sr1);
            si1 = fmaf(xr1[p],  c.z, si1); si1 = fmaf(xi1[p],  c.y, si1);
        }
        // ss = e^{2m} * (sr'^2 + si'^2 + eps),  m = max_p mag
        float ss0  = fmaf(sr0, sr0, fmaf(si0, si0, 0.001f * wm0 * wm0));
        float ss1  = fmaf(sr1, sr1, fmaf(si1, si1, 0.001f * wm1 * wm1));
        float iv0 = rsqrtf(ss0), iv1 = rsqrtf(ss1);
        float bias = sbias[lf];
        float2 mg = make_float2(0.5f * __logf(ss0) - LOG_NPEAKS + bias,
                                0.5f * __logf(ss1) - LOG_NPEAKS + bias);
        float2 dr = make_float2(sr0 * iv0, sr1 * iv1);
        float2 di = make_float2(si0 * iv0, si1 * iv1);

        *(float2*)magp         = mg;
        *(float2*)dirp         = dr;
        *(float2*)(dirp + PIX) = di;
        magp += PIX;
        dirp += 2 * PIX;
    }
}

extern "C" void kernel_launch(void* const* d_in, const int* in_sizes, int n_in,
                              void* d_out, int out_size) {
    const float* shapes = (const float*)d_in[0];  // (4,3,16,64,64)
    const float* resp   = (const float*)d_in[1];  // (4,100,3,16)
    const float* freqs  = (const float*)d_in[2];  // (4,100)
    float* out = (float*)d_out;

    prep_kernel<<<563, TPB>>>(shapes, resp, freqs, out + AUX_OFF);
    dim3 grid(PIX / (TPB * PPT), B_SZ, NFC);
    field_kernel<<<grid, TPB>>>(shapes, out);
}